// round 15
// baseline (speedup 1.0000x reference)
#include <cuda_runtime.h>
#include <math.h>

#define S_   2
#define C_   256
#define KD_  128
#define CE_  16
#define F_   5
#define HW_  2304
#define LK_  (F_*HW_)
#define TAU_INV 30.0f
#define LOG2E 1.4426950408889634f
#define CBIAS (30.0f * LOG2E)

typedef unsigned long long u64;

__device__ __forceinline__ u64 pack2(float x) {
    u64 r; asm("mov.b64 %0, {%1, %1};" : "=l"(r) : "f"(x)); return r;
}
__device__ __forceinline__ void unpack2(u64 v, float &x, float &y) {
    asm("mov.b64 {%0, %1}, %2;" : "=f"(x), "=f"(y) : "l"(v));
}
__device__ __forceinline__ void fma2(u64 &d, u64 a, u64 b) {
    asm("fma.rn.f32x2 %0, %1, %2, %0;" : "+l"(d) : "l"(a), "l"(b));
}
__device__ __forceinline__ u64 add2(u64 a, u64 b) {
    u64 r; asm("add.rn.f32x2 %0, %1, %2;" : "=l"(r) : "l"(a), "l"(b)); return r;
}
__device__ __forceinline__ void cp16(float* dst, const float* src) {
    unsigned sa = (unsigned)__cvta_generic_to_shared(dst);
    asm volatile("cp.async.cg.shared.global [%0], [%1], 16;" :: "r"(sa), "l"(src));
}
#define CP_COMMIT() asm volatile("cp.async.commit_group;" ::: "memory")
#define CP_WAIT1()  asm volatile("cp.async.wait_group 1;" ::: "memory")
#define CP_WAIT0()  asm volatile("cp.async.wait_group 0;" ::: "memory")

__device__ float g_wq [S_*HW_*KD_];
__device__ float g_wv [S_*HW_*C_];
__device__ float g_y  [S_*C_*HW_];
__device__ float g_wq2[S_*HW_*KD_];
__device__ float g_wk2[S_*LK_*KD_];
__device__ float g_wv2[S_*LK_*CE_];
__device__ float g_mu [S_*C_];
__device__ float g_rs [S_*C_];
__device__ float g_wf [S_*KD_*C_];
__device__ float g_bf [S_*KD_];

// ============================ proj2: 2D register-tiled projection (R12) ============================
#define P2PITCH 260
#define P2_SHW  0
#define P2_SHIN (128*P2PITCH)
#define P2_NRM  (128*P2PITCH + 32*P2PITCH)
#define P2_TOT  (128*P2PITCH + 32*P2PITCH + 128)

template<int MODE, bool NORM>
__global__ void __launch_bounds__(256, 1)
proj2_kernel(const float* __restrict__ in, const float* __restrict__ Wg,
             const float* __restrict__ Bg, float* __restrict__ out,
             int P, int wstride, int bstride, int Jtot)
{
    extern __shared__ float smp[];
    const int s  = blockIdx.y;
    const int jh = blockIdx.z;
    const int p0 = blockIdx.x * 32;
    const int tid = threadIdx.x, w = tid >> 5, l = tid & 31;
    const int pg = w >> 2, jg = w & 3;
    const int pi = l >> 3, ji = l & 7;

    const float* Wp = Wg + (long)s * wstride + (long)jh * 128 * C_;
    const float* Bp = Bg + (long)s * bstride + jh * 128;

    for (int idx = tid; idx < 128 * 64; idx += 256) {
        int j = idx >> 6, c = idx & 63;
        cp16(smp + P2_SHW + j * P2PITCH + 4 * c, Wp + (long)j * C_ + 4 * c);
    }
    CP_COMMIT();

    {
        int pl = tid & 31, g = tid >> 5;
        long base, stride;
        if (MODE == 0) {
            base = ((long)s * C_) * P + p0 + pl;
            stride = P;
        } else {
            int f = p0 / HW_;
            int hw = p0 - f * HW_ + pl;
            base = ((long)((f * 2 + s) * C_)) * HW_ + hw;
            stride = HW_;
        }
#pragma unroll
        for (int cc = 0; cc < 8; cc++) {
            int i0 = 32 * g + 4 * cc;
            float4 v;
            v.x = in[base + (long)(i0 + 0) * stride];
            v.y = in[base + (long)(i0 + 1) * stride];
            v.z = in[base + (long)(i0 + 2) * stride];
            v.w = in[base + (long)(i0 + 3) * stride];
            *(float4*)(smp + P2_SHIN + pl * P2PITCH + i0) = v;
        }
    }
    CP_WAIT0();
    __syncthreads();

    u64 sc[4][4];
#pragma unroll
    for (int i = 0; i < 4; i++)
#pragma unroll
        for (int m = 0; m < 4; m++) sc[i][m] = 0ull;

    const float* pb = smp + P2_SHIN + (16 * pg + pi) * P2PITCH;
    const float* wb = smp + P2_SHW  + (32 * jg + ji) * P2PITCH;
#pragma unroll 2
    for (int u = 0; u < 64; u++) {
        ulonglong2 a[4], b[4];
#pragma unroll
        for (int i = 0; i < 4; i++)
            a[i] = *(const ulonglong2*)(pb + (4 * i) * P2PITCH + 4 * u);
#pragma unroll
        for (int m = 0; m < 4; m++)
            b[m] = *(const ulonglong2*)(wb + (8 * m) * P2PITCH + 4 * u);
#pragma unroll
        for (int i = 0; i < 4; i++)
#pragma unroll
            for (int m = 0; m < 4; m++) {
                fma2(sc[i][m], a[i].x, b[m].x);
                fma2(sc[i][m], a[i].y, b[m].y);
            }
    }

    float bj[4];
#pragma unroll
    for (int m = 0; m < 4; m++) bj[m] = Bp[32 * jg + 8 * m + ji];

    float val[4][4];
#pragma unroll
    for (int i = 0; i < 4; i++)
#pragma unroll
        for (int m = 0; m < 4; m++) {
            float x, yv; unpack2(sc[i][m], x, yv);
            val[i][m] = x + yv + bj[m];
        }

    if (NORM) {
        float ss[4];
#pragma unroll
        for (int i = 0; i < 4; i++) {
            float t = 0.f;
#pragma unroll
            for (int m = 0; m < 4; m++) t += val[i][m] * val[i][m];
            ss[i] = t;
        }
#pragma unroll
        for (int off = 4; off; off >>= 1)
#pragma unroll
            for (int i = 0; i < 4; i++)
                ss[i] += __shfl_xor_sync(0xffffffffu, ss[i], off);
        if (ji == 0) {
#pragma unroll
            for (int i = 0; i < 4; i++)
                smp[P2_NRM + jg * 32 + 16 * pg + pi + 4 * i] = ss[i];
        }
        __syncthreads();
#pragma unroll
        for (int i = 0; i < 4; i++) {
            int pp = 16 * pg + pi + 4 * i;
            float tot = smp[P2_NRM + pp] + smp[P2_NRM + 32 + pp]
                      + smp[P2_NRM + 64 + pp] + smp[P2_NRM + 96 + pp];
            float rn = 1.f / fmaxf(sqrtf(tot), 1e-12f);
            long ob = ((long)s * P + p0 + pp) * Jtot + jh * 128;
#pragma unroll
            for (int m = 0; m < 4; m++)
                out[ob + 32 * jg + 8 * m + ji] = val[i][m] * rn;
        }
    } else {
#pragma unroll
        for (int i = 0; i < 4; i++) {
            int pp = 16 * pg + pi + 4 * i;
            long ob = ((long)s * P + p0 + pp) * Jtot + jh * 128;
#pragma unroll
            for (int m = 0; m < 4; m++)
                out[ob + 32 * jg + 8 * m + ji] = val[i][m];
        }
    }
}

// ============================ old projection (J=16 pos-proj) ============================
template<int J, int MODE, bool NORM>
__global__ void proj_kernel(const float* __restrict__ in, const float* __restrict__ W,
                            const float* __restrict__ B, float* __restrict__ out,
                            int Cin, int P, int wstride, int bstride)
{
    constexpr int PB = 16;
    constexpr int PperT = J / 16;
    const int s  = blockIdx.y;
    const int p0 = blockIdx.x * PB;
    const int tid = threadIdx.x;

    __shared__ float shIn[256 * 16];

    for (int idx = tid; idx < Cin * PB; idx += 256) {
        int i = idx >> 4, pl = idx & 15, p = p0 + pl;
        long off;
        if (MODE == 0) off = ((long)(s * Cin + i)) * P + p;
        else { int f = p / HW_, hw = p - f * HW_;
               off = ((long)((f * 2 + s) * Cin + i)) * HW_ + hw; }
        shIn[idx] = in[off];
    }
    __syncthreads();

    const int j  = tid % J;
    const int pg = tid / J;
    const int pbase = pg * PperT;
    const float b = B[(long)s * bstride + j];
    const float* Wr = W + (long)s * wstride + (long)j * Cin;

    float acc = 0.f;
#pragma unroll 4
    for (int i = 0; i < Cin; i++) acc += Wr[i] * shIn[i * 16 + pbase];
    int p = p0 + pbase;
    out[((long)s * P + p) * J + j] = acc + b;
}

// ============================ self attention (R8/R10, unchanged) ============================
#define SFK 0
#define SFKSTR 8448
#define SFV 16896
#define SFVSTR 16384
#define SFQ 49664
#define SFP 53760
#define SFL 55840
#define SF_TOT 55904
#define SF_NT 36

__device__ __forceinline__ void self_prefetch(float* sm, int buf, const float* wqs,
                                              const float* wvs, int k0, int tid)
{
    float* Kb = sm + SFK + buf * SFKSTR;
    float* Vb = sm + SFV + buf * SFVSTR;
#pragma unroll
    for (int r = 0; r < 8; r++) {
        int idx = r * 256 + tid;
        int k = idx >> 5, u = idx & 31;
        cp16(Kb + k * 132 + 4 * u, wqs + (long)(k0 + k) * KD_ + 4 * u);
    }
#pragma unroll
    for (int r = 0; r < 16; r++) {
        int idx = r * 256 + tid;
        int k = idx >> 6, u = idx & 63;
        cp16(Vb + k * 256 + 4 * u, wvs + (long)(k0 + k) * C_ + 4 * u);
    }
}

__global__ void __launch_bounds__(256, 1)
self_attn_kernel(const float* __restrict__ wq, const float* __restrict__ wv,
                 const float* __restrict__ tgt, float* __restrict__ y)
{
    extern __shared__ float sm[];
    const int s = blockIdx.y, q0 = blockIdx.x * 32;
    const int tid = threadIdx.x, w = tid >> 5, l = tid & 31;
    const int qg = w >> 1, kh = w & 1;
    const float* wqs = wq + (long)s * HW_ * KD_;
    const float* wvs = wv + (long)s * HW_ * C_;

#pragma unroll
    for (int r = 0; r < 4; r++) {
        int idx = r * 256 + tid;
        int q = idx >> 5, u = idx & 31;
        float4 v = *(const float4*)(wqs + (long)(q0 + q) * KD_ + 4 * u);
        v.x *= TAU_INV; v.y *= TAU_INV; v.z *= TAU_INV; v.w *= TAU_INV;
        *(float4*)(sm + SFQ + q * 128 + 4 * u) = v;
    }
    self_prefetch(sm, 0, wqs, wvs, 0, tid);
    CP_COMMIT();

    float lpart = 0.f;
    u64 acc[8][4];
#pragma unroll
    for (int i = 0; i < 8; i++)
#pragma unroll
        for (int jj = 0; jj < 4; jj++) acc[i][jj] = 0ull;

    for (int kt = 0; kt < SF_NT; kt++) {
        const int cur = kt & 1;
        __syncthreads();
        if (kt + 1 < SF_NT)
            self_prefetch(sm, cur ^ 1, wqs, wvs, (kt + 1) * 64, tid);
        CP_COMMIT();
        CP_WAIT1();
        __syncthreads();

        const float* Kb = sm + SFK + cur * SFKSTR;
        const float* Vb = sm + SFV + cur * SFVSTR;

        u64 sc[8];
#pragma unroll
        for (int i = 0; i < 8; i++) sc[i] = 0ull;
        const float* krow = Kb + (32 * kh + l) * 132;
#pragma unroll 4
        for (int u = 0; u < 32; u++) {
            ulonglong2 ka = *(const ulonglong2*)(krow + 4 * u);
#pragma unroll
            for (int i = 0; i < 8; i++) {
                ulonglong2 qv = *(const ulonglong2*)(sm + SFQ + (8 * qg + i) * 128 + 4 * u);
                fma2(sc[i], qv.x, ka.x); fma2(sc[i], qv.y, ka.y);
            }
        }
#pragma unroll
        for (int i = 0; i < 8; i++) {
            float x, yv; unpack2(sc[i], x, yv);
            float p = __expf((x + yv) - 30.f);
            sm[SFP + (8 * qg + i) * 65 + 32 * kh + l] = p;
            float ps = p;
#pragma unroll
            for (int off = 16; off; off >>= 1)
                ps += __shfl_xor_sync(0xffffffffu, ps, off);
            if (l == i) lpart += ps;
        }
        __syncthreads();

#pragma unroll 2
        for (int kk = 0; kk < 32; kk++) {
            const int k = 32 * kh + kk;
            u64 pk[8];
#pragma unroll
            for (int i = 0; i < 8; i++)
                pk[i] = pack2(sm[SFP + (8 * qg + i) * 65 + k]);
            const float* vr = Vb + k * 256 + 2 * l;
#pragma unroll
            for (int jj = 0; jj < 4; jj++) {
                u64 vv = *(const u64*)(vr + 64 * jj);
#pragma unroll
                for (int i = 0; i < 8; i++) fma2(acc[i][jj], pk[i], vv);
            }
        }
    }

    __syncthreads();
    u64* sbuf = reinterpret_cast<u64*>(sm + SFK);
    float* lbuf = sm + SFL;
    if (kh == 0) {
#pragma unroll
        for (int i = 0; i < 8; i++)
#pragma unroll
            for (int jj = 0; jj < 4; jj++)
                sbuf[((qg * 32 + l) * 33) + i * 4 + jj] = acc[i][jj];
        if (l < 8) lbuf[qg * 8 + l] = lpart;
    }
    __syncthreads();
    if (kh == 1) {
#pragma unroll
        for (int i = 0; i < 8; i++) {
            float tot_l = __shfl_sync(0xffffffffu, lpart, i) + lbuf[qg * 8 + i];
            float inv = 1.f / tot_l;
            int p = q0 + 8 * qg + i;
#pragma unroll
            for (int jj = 0; jj < 4; jj++) {
                u64 t = add2(acc[i][jj], sbuf[((qg * 32 + l) * 33) + i * 4 + jj]);
                float x, yv; unpack2(t, x, yv);
                int d = 2 * l + 64 * jj;
                long b0 = ((long)(s * C_ + d)) * HW_ + p;
                y[b0]       = x * inv + tgt[b0];
                y[b0 + HW_] = yv * inv + tgt[b0 + HW_];
            }
        }
    }
}

// ============================ instnorm + fold (unchanged) ============================
__global__ void instnorm_stats_kernel(const float* __restrict__ y,
                                      float* __restrict__ mu, float* __restrict__ rs)
{
    const int sc = blockIdx.x;
    const float* row = y + (long)sc * HW_;
    float sum = 0.f, ss = 0.f;
    for (int p = threadIdx.x; p < HW_; p += 256) {
        float v = row[p]; sum += v; ss += v * v;
    }
    __shared__ float s1[256], s2[256];
    s1[threadIdx.x] = sum; s2[threadIdx.x] = ss;
    __syncthreads();
    for (int st = 128; st > 0; st >>= 1) {
        if (threadIdx.x < st) {
            s1[threadIdx.x] += s1[threadIdx.x + st];
            s2[threadIdx.x] += s2[threadIdx.x + st];
        }
        __syncthreads();
    }
    if (threadIdx.x == 0) {
        float m = s1[0] / (float)HW_;
        float var = s2[0] / (float)HW_ - m * m;
        mu[sc] = m; rs[sc] = rsqrtf(var + 1e-5f);
    }
}

__global__ void fold_kernel(const float* __restrict__ WK, const float* __restrict__ bK,
                            const float* __restrict__ mu, const float* __restrict__ rs,
                            float* __restrict__ Wf, float* __restrict__ bf)
{
    const int j = blockIdx.x, s = blockIdx.y, tid = threadIdx.x;
    float w = WK[j * C_ + tid] * rs[s * C_ + tid];
    Wf[((long)(s * KD_ + j)) * C_ + tid] = w;
    __shared__ float red[256];
    red[tid] = w * mu[s * C_ + tid];
    __syncthreads();
    for (int st = 128; st > 0; st >>= 1) {
        if (tid < st) red[tid] += red[tid + st];
        __syncthreads();
    }
    if (tid == 0) bf[s * KD_ + j] = bK[j] - red[0];
}

// ============================ cross attention: 512 threads, 16 warps ============================
// Grid (72, S). 16 warps = (qg 0..1) x (kg 0..7). Warp = 16q x 16k of 128-key tile.
// Lane (qi=l>>3, ki=l&7): queries {16qg+qi+4i}, keys {16kg+ki+8m}, m=0..1.
// Q prescaled by TAU_INV*LOG2E; p = exp2f(s - 30*LOG2E).
#define CRK 0
#define CRKSTR 16896          // 128*132
#define CRV 33792
#define CRVSTR 2560           // 128*20
#define CRQ 38912             // 32*132
#define CRM 43136             // 2048 u64 (4096 f) + 256 f lsum
#define CR_TOT 47488          // floats = 189952 B
#define CR_NT 90

__device__ __forceinline__ void cross_prefetch(float* sm, int buf, const float* wks,
                                               const float* wvs, int k0, int tid)
{
    float* Kb = sm + CRK + buf * CRKSTR;
    float* Vb = sm + CRV + buf * CRVSTR;
#pragma unroll
    for (int r = 0; r < 8; r++) {                 // 4096 float4
        int idx = r * 512 + tid;
        int k = idx >> 5, u = idx & 31;
        cp16(Kb + k * 132 + 4 * u, wks + (long)(k0 + k) * KD_ + 4 * u);
    }
    {                                             // 512 float4
        int idx = tid;
        int k = idx >> 2, j = idx & 3;
        cp16(Vb + k * 20 + 4 * j, wvs + (long)(k0 + k) * CE_ + 4 * j);
    }
}

__global__ void __launch_bounds__(512, 1)
cross_attn_kernel(const float* __restrict__ wq2, const float* __restrict__ wk2,
                  const float* __restrict__ wv2, float* __restrict__ out)
{
    extern __shared__ float sm[];
    const int s = blockIdx.y, q0 = blockIdx.x * 32;
    const int tid = threadIdx.x, w = tid >> 5, l = tid & 31;
    const int qg = w >> 3, kg = w & 7;
    const int qi = l >> 3, ki = l & 7;
    const float* wqs = wq2 + (long)s * HW_ * KD_;
    const float* wks = wk2 + (long)s * LK_ * KD_;
    const float* wvs = wv2 + (long)s * LK_ * CE_;

    // stage Q (prescaled by 30*log2e), pitch 132
    const float qscale = TAU_INV * LOG2E;
#pragma unroll
    for (int r = 0; r < 2; r++) {
        int idx = r * 512 + tid;
        int q = idx >> 5, u = idx & 31;
        float4 v = *(const float4*)(wqs + (long)(q0 + q) * KD_ + 4 * u);
        v.x *= qscale; v.y *= qscale; v.z *= qscale; v.w *= qscale;
        *(float4*)(sm + CRQ + q * 132 + 4 * u) = v;
    }
    cross_prefetch(sm, 0, wks, wvs, 0, tid);
    CP_COMMIT();

    float lsum[4] = {0.f, 0.f, 0.f, 0.f};
    u64 acc[4][8];
#pragma unroll
    for (int i = 0; i < 4; i++)
#pragma unroll
        for (int jj = 0; jj < 8; jj++) acc[i][jj] = 0ull;

    const float* qbase = sm + CRQ + (16 * qg + qi) * 132;
    for (int kt = 0; kt < CR_NT; kt++) {
        const int cur = kt & 1;
        __syncthreads();
        if (kt + 1 < CR_NT)
            cross_prefetch(sm, cur ^ 1, wks, wvs, (kt + 1) * 128, tid);
        CP_COMMIT();
        CP_WAIT1();
        __syncthreads();

        const float* Kb = sm + CRK + cur * CRKSTR + (16 * kg + ki) * 132;
        const float* Vb = sm + CRV + cur * CRVSTR + (16 * kg + ki) * 20;

        // ---- scores: 4q x 2k per lane ----
        u64 sc[4][2];
#pragma unroll
        for (int i = 0; i < 4; i++) { sc[i][0] = 0ull; sc[i][1] = 0ull; }

#pragma unroll 4
        for (int u = 0; u < 32; u++) {
            ulonglong2 qch[4], kch[2];
#pragma unroll
            for (int i = 0; i < 4; i++)
                qch[i] = *(const ulonglong2*)(qbase + (4 * i) * 132 + 4 * u);
#pragma unroll
            for (int m = 0; m < 2; m++)
                kch[m] = *(const ulonglong2*)(Kb + (8 * m) * 132 + 4 * u);
#pragma unroll
            for (int i = 0; i < 4; i++)
#pragma unroll
                for (int m = 0; m < 2; m++) {
                    fma2(sc[i][m], qch[i].x, kch[m].x);
                    fma2(sc[i][m], qch[i].y, kch[m].y);
                }
        }

        // ---- exp2 + PV ----
#pragma unroll
        for (int m = 0; m < 2; m++) {
            const float* vr = Vb + (8 * m) * 20;
            ulonglong2 vA = *(const ulonglong2*)(vr);
            ulonglong2 vB = *(const ulonglong2*)(vr + 4);
            ulonglong2 vC = *(const ulonglong2*)(vr + 8);
            ulonglong2 vD = *(const ulonglong2*)(vr + 12);
#pragma unroll
            for (int i = 0; i < 4; i++) {
                float x, yv; unpack2(sc[i][m], x, yv);
                float p = exp2f((x + yv) - CBIAS);
                lsum[i] += p;
                u64 pk = pack2(p);
                fma2(acc[i][0], pk, vA.x); fma2(acc[i][1], pk, vA.y);
                fma2(acc[i][2], pk, vB.x); fma2(acc[i][3], pk, vB.y);
                fma2(acc[i][4], pk, vC.x); fma2(acc[i][5], pk, vC.y);
                fma2(acc[i][6], pk, vD.x); fma2(acc[i][7], pk, vD.y);
            }
        }
    }

    // ---- butterfly over ki (bits 0..2) ----
#pragma unroll
    for (int off = 4; off; off >>= 1) {
#pragma unroll
        for (int i = 0; i < 4; i++) {
            lsum[i] += __shfl_xor_sync(0xffffffffu, lsum[i], off);
#pragma unroll
            for (int jj = 0; jj < 8; jj++)
                acc[i][jj] = add2(acc[i][jj],
                                  __shfl_xor_sync(0xffffffffu, acc[i][jj], off));
        }
    }

    // ---- kg merge via smem (16 groups) ----
    __syncthreads();
    u64*  mrg  = reinterpret_cast<u64*>(sm + CRM);     // [(qg*8+kg)*16 + qloc][8]
    float* mrgL = sm + CRM + 4096;                      // 256 entries
    if (ki == 0) {
#pragma unroll
        for (int i = 0; i < 4; i++) {
            int qloc = 4 * i + qi;
            int base = ((qg * 8 + kg) * 16 + qloc) * 8;
#pragma unroll
            for (int jj = 0; jj < 8; jj++) mrg[base + jj] = acc[i][jj];
            mrgL[(qg * 8 + kg) * 16 + qloc] = lsum[i];
        }
    }
    __syncthreads();
    if (tid < 256) {
        int q32 = tid >> 3, dp = tid & 7;
        int qg2 = q32 >> 4, qloc = q32 & 15;
        u64 tot = 0ull;
        float lt = 0.f;
#pragma unroll
        for (int g = 0; g < 8; g++) {
            tot = add2(tot, mrg[((qg2 * 8 + g) * 16 + qloc) * 8 + dp]);
            lt += mrgL[(qg2 * 8 + g) * 16 + qloc];
        }
        float inv = 1.f / lt;
        float x, yv; unpack2(tot, x, yv);
        int p = q0 + q32;
        out[((long)(s * CE_ + 2 * dp    )) * HW_ + p] = x * inv;
        out[((long)(s * CE_ + 2 * dp + 1)) * HW_ + p] = yv * inv;
    }
}

// ============================ launcher ============================
extern "C" void kernel_launch(void* const* d_in, const int* in_sizes, int n_in,
                              void* d_out, int out_size)
{
    const float* tgt    = (const float*)d_in[0];
    const float* memory = (const float*)d_in[1];
    const float* pos    = (const float*)d_in[2];
    const float* WKs_w  = (const float*)d_in[3];
    const float* WKs_b  = (const float*)d_in[4];
    const float* WVs_w  = (const float*)d_in[5];
    const float* WVs_b  = (const float*)d_in[6];
    const float* WKc_w  = (const float*)d_in[7];
    const float* WKc_b  = (const float*)d_in[8];
    const float* WVc_w  = (const float*)d_in[9];
    const float* WVc_b  = (const float*)d_in[10];
    float* out = (float*)d_out;

    float *p_wq, *p_wv, *p_y, *p_wq2, *p_wk2, *p_wv2, *p_mu, *p_rs, *p_wf, *p_bf;
    cudaGetSymbolAddress((void**)&p_wq,  g_wq);
    cudaGetSymbolAddress((void**)&p_wv,  g_wv);
    cudaGetSymbolAddress((void**)&p_y,   g_y);
    cudaGetSymbolAddress((void**)&p_wq2, g_wq2);
    cudaGetSymbolAddress((void**)&p_wk2, g_wk2);
    cudaGetSymbolAddress((void**)&p_wv2, g_wv2);
    cudaGetSymbolAddress((void**)&p_mu,  g_mu);
    cudaGetSymbolAddress((void**)&p_rs,  g_rs);
    cudaGetSymbolAddress((void**)&p_wf,  g_wf);
    cudaGetSymbolAddress((void**)&p_bf,  g_bf);

    const int SELF_SH  = SF_TOT * 4;
    const int CROSS_SH = CR_TOT * 4;   // 189952 B
    const int PROJ_SH  = P2_TOT * 4;
    cudaFuncSetAttribute(self_attn_kernel,  cudaFuncAttributeMaxDynamicSharedMemorySize, SELF_SH);
    cudaFuncSetAttribute(cross_attn_kernel, cudaFuncAttributeMaxDynamicSharedMemorySize, CROSS_SH);
    cudaFuncSetAttribute(proj2_kernel<0, true >, cudaFuncAttributeMaxDynamicSharedMemorySize, PROJ_SH);
    cudaFuncSetAttribute(proj2_kernel<0, false>, cudaFuncAttributeMaxDynamicSharedMemorySize, PROJ_SH);
    cudaFuncSetAttribute(proj2_kernel<1, true >, cudaFuncAttributeMaxDynamicSharedMemorySize, PROJ_SH);

    proj2_kernel<0, true ><<<dim3(HW_/32, S_, 1), 256, PROJ_SH>>>(tgt, WKs_w, WKs_b, p_wq, HW_, 0, 0, 128);
    proj2_kernel<0, false><<<dim3(HW_/32, S_, 2), 256, PROJ_SH>>>(tgt, WVs_w, WVs_b, p_wv, HW_, 0, 0, 256);
    proj_kernel<16, 1, false><<<dim3(LK_/16, S_), 256>>>(pos, WVc_w, WVc_b, p_wv2, CE_, LK_, 0, 0);
    proj2_kernel<1, true ><<<dim3(LK_/32, S_, 1), 256, PROJ_SH>>>(memory, WKc_w, WKc_b, p_wk2, LK_, 0, 0, 128);
    self_attn_kernel<<<dim3(HW_/32, S_), 256, SELF_SH>>>(p_wq, p_wv, tgt, p_y);
    instnorm_stats_kernel<<<S_*C_, 256>>>(p_y, p_mu, p_rs);
    fold_kernel<<<dim3(KD_, S_), 256>>>(WKc_w, WKc_b, p_mu, p_rs, p_wf, p_bf);
    proj2_kernel<0, true ><<<dim3(HW_/32, S_, 1), 256, PROJ_SH>>>(p_y, p_wf, p_bf, p_wq2, HW_, KD_*C_, KD_, 128);
    cross_attn_kernel<<<dim3(HW_/32, S_), 512, CROSS_SH>>>(p_wq2, p_wk2, p_wv2, out);
}

// round 16
// speedup vs baseline: 1.1119x; 1.1119x over previous
#include <cuda_runtime.h>
#include <math.h>

#define S_   2
#define C_   256
#define KD_  128
#define CE_  16
#define F_   5
#define HW_  2304
#define LK_  (F_*HW_)
#define TAU_INV 30.0f
#define LOG2E 1.4426950408889634f
#define CBIAS (30.0f * LOG2E)

typedef unsigned long long u64;

__device__ __forceinline__ u64 pack2(float x) {
    u64 r; asm("mov.b64 %0, {%1, %1};" : "=l"(r) : "f"(x)); return r;
}
__device__ __forceinline__ void unpack2(u64 v, float &x, float &y) {
    asm("mov.b64 {%0, %1}, %2;" : "=f"(x), "=f"(y) : "l"(v));
}
__device__ __forceinline__ void fma2(u64 &d, u64 a, u64 b) {
    asm("fma.rn.f32x2 %0, %1, %2, %0;" : "+l"(d) : "l"(a), "l"(b));
}
__device__ __forceinline__ u64 add2(u64 a, u64 b) {
    u64 r; asm("add.rn.f32x2 %0, %1, %2;" : "=l"(r) : "l"(a), "l"(b)); return r;
}
__device__ __forceinline__ void cp16(float* dst, const float* src) {
    unsigned sa = (unsigned)__cvta_generic_to_shared(dst);
    asm volatile("cp.async.cg.shared.global [%0], [%1], 16;" :: "r"(sa), "l"(src));
}
#define CP_COMMIT() asm volatile("cp.async.commit_group;" ::: "memory")
#define CP_WAIT1()  asm volatile("cp.async.wait_group 1;" ::: "memory")
#define CP_WAIT0()  asm volatile("cp.async.wait_group 0;" ::: "memory")

__device__ float g_wq [S_*HW_*KD_];
__device__ float g_wv [S_*HW_*C_];
__device__ float g_y  [S_*C_*HW_];
__device__ float g_wq2[S_*HW_*KD_];
__device__ float g_wk2[S_*LK_*KD_];
__device__ float g_wv2[S_*LK_*CE_];
__device__ float g_mu [S_*C_];
__device__ float g_rs [S_*C_];
__device__ float g_wf [S_*KD_*C_];
__device__ float g_bf [S_*KD_];

// ============================ proj2: 2D register-tiled projection, 64p per block ============================
// out(s,p,j) = (opt l2norm_j)( sum_i in(s,i,p)*W[j][i] + b[j] ),  Cin = 256, 128 j per block.
// Block: 256 thr = (pg 0..1) x (jg 0..3) warps; warp = 32p x 32j; lane (pi=l>>3, ji=l&7): 8p x 4j.
// smem: shW[128][260] (staged once) | shIn[64][260] | nrm[4][64]
#define P2PITCH 260
#define P2_SHW  0
#define P2_SHIN (128*P2PITCH)                 // 33280
#define P2_NRM  (P2_SHIN + 64*P2PITCH)        // 49920
#define P2_TOT  (P2_NRM + 256)                // 50176 floats = 200704 B

template<int MODE, bool NORM>
__global__ void __launch_bounds__(256, 1)
proj2_kernel(const float* __restrict__ in, const float* __restrict__ Wg,
             const float* __restrict__ Bg, float* __restrict__ out,
             int P, int wstride, int bstride, int Jtot)
{
    extern __shared__ float smp[];
    const int s  = blockIdx.y;
    const int jh = blockIdx.z;                 // j-half for Jtot=256 (else 0)
    const int p0 = blockIdx.x * 64;
    const int tid = threadIdx.x, w = tid >> 5, l = tid & 31;
    const int pg = w >> 2, jg = w & 3;
    const int pi = l >> 3, ji = l & 7;

    const float* Wp = Wg + (long)s * wstride + (long)jh * 128 * C_;
    const float* Bp = Bg + (long)s * bstride + jh * 128;

    // ---- stage W [128][260] via cp.async (once per block) ----
    for (int idx = tid; idx < 128 * 64; idx += 256) {
        int j = idx >> 6, c = idx & 63;
        cp16(smp + P2_SHW + j * P2PITCH + 4 * c, Wp + (long)j * C_ + 4 * c);
    }
    CP_COMMIT();

    // ---- stage input tile transposed: shIn[p][i], 64 rows, pitch 260 ----
    {
        int pl = tid & 63, g = tid >> 6;       // thread covers i in [64g, 64g+64)
        long base, stride;
        if (MODE == 0) {
            base = ((long)s * C_) * P + p0 + pl;
            stride = P;
        } else {
            int f = p0 / HW_;                  // p0 mult of 64; HW_ = 36*64 -> block within one frame
            int hw = p0 - f * HW_ + pl;
            base = ((long)((f * 2 + s) * C_)) * HW_ + hw;
            stride = HW_;
        }
#pragma unroll
        for (int cc = 0; cc < 16; cc++) {
            int i0 = 64 * g + 4 * cc;
            float4 v;
            v.x = in[base + (long)(i0 + 0) * stride];
            v.y = in[base + (long)(i0 + 1) * stride];
            v.z = in[base + (long)(i0 + 2) * stride];
            v.w = in[base + (long)(i0 + 3) * stride];
            *(float4*)(smp + P2_SHIN + pl * P2PITCH + i0) = v;
        }
    }
    CP_WAIT0();
    __syncthreads();

    // ---- compute 8p x 4j, i-paired f32x2 ----
    u64 sc[8][4];
#pragma unroll
    for (int i = 0; i < 8; i++)
#pragma unroll
        for (int m = 0; m < 4; m++) sc[i][m] = 0ull;

    const float* pb = smp + P2_SHIN + (32 * pg + pi) * P2PITCH;   // + 4i*pitch
    const float* wb = smp + P2_SHW  + (32 * jg + ji) * P2PITCH;   // + 8m*pitch
#pragma unroll 2
    for (int u = 0; u < 64; u++) {
        ulonglong2 a[8], b[4];
#pragma unroll
        for (int i = 0; i < 8; i++)
            a[i] = *(const ulonglong2*)(pb + (4 * i) * P2PITCH + 4 * u);
#pragma unroll
        for (int m = 0; m < 4; m++)
            b[m] = *(const ulonglong2*)(wb + (8 * m) * P2PITCH + 4 * u);
#pragma unroll
        for (int i = 0; i < 8; i++)
#pragma unroll
            for (int m = 0; m < 4; m++) {
                fma2(sc[i][m], a[i].x, b[m].x);
                fma2(sc[i][m], a[i].y, b[m].y);
            }
    }

    // ---- epilogue: bias, optional l2norm over j, store ----
    float bj[4];
#pragma unroll
    for (int m = 0; m < 4; m++) bj[m] = Bp[32 * jg + 8 * m + ji];

    float val[8][4];
#pragma unroll
    for (int i = 0; i < 8; i++)
#pragma unroll
        for (int m = 0; m < 4; m++) {
            float x, yv; unpack2(sc[i][m], x, yv);
            val[i][m] = x + yv + bj[m];
        }

    if (NORM) {
        float ss[8];
#pragma unroll
        for (int i = 0; i < 8; i++) {
            float t = 0.f;
#pragma unroll
            for (int m = 0; m < 4; m++) t += val[i][m] * val[i][m];
            ss[i] = t;
        }
#pragma unroll
        for (int off = 4; off; off >>= 1)
#pragma unroll
            for (int i = 0; i < 8; i++)
                ss[i] += __shfl_xor_sync(0xffffffffu, ss[i], off);
        if (ji == 0) {
#pragma unroll
            for (int i = 0; i < 8; i++)
                smp[P2_NRM + jg * 64 + 32 * pg + pi + 4 * i] = ss[i];
        }
        __syncthreads();
#pragma unroll
        for (int i = 0; i < 8; i++) {
            int pp = 32 * pg + pi + 4 * i;
            float tot = smp[P2_NRM + pp] + smp[P2_NRM + 64 + pp]
                      + smp[P2_NRM + 128 + pp] + smp[P2_NRM + 192 + pp];
            float rn = 1.f / fmaxf(sqrtf(tot), 1e-12f);
            long ob = ((long)s * P + p0 + pp) * Jtot + jh * 128;
#pragma unroll
            for (int m = 0; m < 4; m++)
                out[ob + 32 * jg + 8 * m + ji] = val[i][m] * rn;
        }
    } else {
#pragma unroll
        for (int i = 0; i < 8; i++) {
            int pp = 32 * pg + pi + 4 * i;
            long ob = ((long)s * P + p0 + pp) * Jtot + jh * 128;
#pragma unroll
            for (int m = 0; m < 4; m++)
                out[ob + 32 * jg + 8 * m + ji] = val[i][m];
        }
    }
}

// ============================ old projection (J=16 pos-proj) ============================
template<int J, int MODE, bool NORM>
__global__ void proj_kernel(const float* __restrict__ in, const float* __restrict__ W,
                            const float* __restrict__ B, float* __restrict__ out,
                            int Cin, int P, int wstride, int bstride)
{
    constexpr int PB = 16;
    constexpr int PperT = J / 16;
    const int s  = blockIdx.y;
    const int p0 = blockIdx.x * PB;
    const int tid = threadIdx.x;

    __shared__ float shIn[256 * 16];

    for (int idx = tid; idx < Cin * PB; idx += 256) {
        int i = idx >> 4, pl = idx & 15, p = p0 + pl;
        long off;
        if (MODE == 0) off = ((long)(s * Cin + i)) * P + p;
        else { int f = p / HW_, hw = p - f * HW_;
               off = ((long)((f * 2 + s) * Cin + i)) * HW_ + hw; }
        shIn[idx] = in[off];
    }
    __syncthreads();

    const int j  = tid % J;
    const int pg = tid / J;
    const int pbase = pg * PperT;
    const float b = B[(long)s * bstride + j];
    const float* Wr = W + (long)s * wstride + (long)j * Cin;

    float acc = 0.f;
#pragma unroll 4
    for (int i = 0; i < Cin; i++) acc += Wr[i] * shIn[i * 16 + pbase];
    int p = p0 + pbase;
    out[((long)s * P + p) * J + j] = acc + b;
}

// ============================ self attention (R8/R10/R12, unchanged) ============================
#define SFK 0
#define SFKSTR 8448
#define SFV 16896
#define SFVSTR 16384
#define SFQ 49664
#define SFP 53760
#define SFL 55840
#define SF_TOT 55904
#define SF_NT 36

__device__ __forceinline__ void self_prefetch(float* sm, int buf, const float* wqs,
                                              const float* wvs, int k0, int tid)
{
    float* Kb = sm + SFK + buf * SFKSTR;
    float* Vb = sm + SFV + buf * SFVSTR;
#pragma unroll
    for (int r = 0; r < 8; r++) {
        int idx = r * 256 + tid;
        int k = idx >> 5, u = idx & 31;
        cp16(Kb + k * 132 + 4 * u, wqs + (long)(k0 + k) * KD_ + 4 * u);
    }
#pragma unroll
    for (int r = 0; r < 16; r++) {
        int idx = r * 256 + tid;
        int k = idx >> 6, u = idx & 63;
        cp16(Vb + k * 256 + 4 * u, wvs + (long)(k0 + k) * C_ + 4 * u);
    }
}

__global__ void __launch_bounds__(256, 1)
self_attn_kernel(const float* __restrict__ wq, const float* __restrict__ wv,
                 const float* __restrict__ tgt, float* __restrict__ y)
{
    extern __shared__ float sm[];
    const int s = blockIdx.y, q0 = blockIdx.x * 32;
    const int tid = threadIdx.x, w = tid >> 5, l = tid & 31;
    const int qg = w >> 1, kh = w & 1;
    const float* wqs = wq + (long)s * HW_ * KD_;
    const float* wvs = wv + (long)s * HW_ * C_;

#pragma unroll
    for (int r = 0; r < 4; r++) {
        int idx = r * 256 + tid;
        int q = idx >> 5, u = idx & 31;
        float4 v = *(const float4*)(wqs + (long)(q0 + q) * KD_ + 4 * u);
        v.x *= TAU_INV; v.y *= TAU_INV; v.z *= TAU_INV; v.w *= TAU_INV;
        *(float4*)(sm + SFQ + q * 128 + 4 * u) = v;
    }
    self_prefetch(sm, 0, wqs, wvs, 0, tid);
    CP_COMMIT();

    float lpart = 0.f;
    u64 acc[8][4];
#pragma unroll
    for (int i = 0; i < 8; i++)
#pragma unroll
        for (int jj = 0; jj < 4; jj++) acc[i][jj] = 0ull;

    for (int kt = 0; kt < SF_NT; kt++) {
        const int cur = kt & 1;
        __syncthreads();
        if (kt + 1 < SF_NT)
            self_prefetch(sm, cur ^ 1, wqs, wvs, (kt + 1) * 64, tid);
        CP_COMMIT();
        CP_WAIT1();
        __syncthreads();

        const float* Kb = sm + SFK + cur * SFKSTR;
        const float* Vb = sm + SFV + cur * SFVSTR;

        u64 sc[8];
#pragma unroll
        for (int i = 0; i < 8; i++) sc[i] = 0ull;
        const float* krow = Kb + (32 * kh + l) * 132;
#pragma unroll 4
        for (int u = 0; u < 32; u++) {
            ulonglong2 ka = *(const ulonglong2*)(krow + 4 * u);
#pragma unroll
            for (int i = 0; i < 8; i++) {
                ulonglong2 qv = *(const ulonglong2*)(sm + SFQ + (8 * qg + i) * 128 + 4 * u);
                fma2(sc[i], qv.x, ka.x); fma2(sc[i], qv.y, ka.y);
            }
        }
#pragma unroll
        for (int i = 0; i < 8; i++) {
            float x, yv; unpack2(sc[i], x, yv);
            float p = __expf((x + yv) - 30.f);
            sm[SFP + (8 * qg + i) * 65 + 32 * kh + l] = p;
            float ps = p;
#pragma unroll
            for (int off = 16; off; off >>= 1)
                ps += __shfl_xor_sync(0xffffffffu, ps, off);
            if (l == i) lpart += ps;
        }
        __syncthreads();

#pragma unroll 2
        for (int kk = 0; kk < 32; kk++) {
            const int k = 32 * kh + kk;
            u64 pk[8];
#pragma unroll
            for (int i = 0; i < 8; i++)
                pk[i] = pack2(sm[SFP + (8 * qg + i) * 65 + k]);
            const float* vr = Vb + k * 256 + 2 * l;
#pragma unroll
            for (int jj = 0; jj < 4; jj++) {
                u64 vv = *(const u64*)(vr + 64 * jj);
#pragma unroll
                for (int i = 0; i < 8; i++) fma2(acc[i][jj], pk[i], vv);
            }
        }
    }

    __syncthreads();
    u64* sbuf = reinterpret_cast<u64*>(sm + SFK);
    float* lbuf = sm + SFL;
    if (kh == 0) {
#pragma unroll
        for (int i = 0; i < 8; i++)
#pragma unroll
            for (int jj = 0; jj < 4; jj++)
                sbuf[((qg * 32 + l) * 33) + i * 4 + jj] = acc[i][jj];
        if (l < 8) lbuf[qg * 8 + l] = lpart;
    }
    __syncthreads();
    if (kh == 1) {
#pragma unroll
        for (int i = 0; i < 8; i++) {
            float tot_l = __shfl_sync(0xffffffffu, lpart, i) + lbuf[qg * 8 + i];
            float inv = 1.f / tot_l;
            int p = q0 + 8 * qg + i;
#pragma unroll
            for (int jj = 0; jj < 4; jj++) {
                u64 t = add2(acc[i][jj], sbuf[((qg * 32 + l) * 33) + i * 4 + jj]);
                float x, yv; unpack2(t, x, yv);
                int d = 2 * l + 64 * jj;
                long b0 = ((long)(s * C_ + d)) * HW_ + p;
                y[b0]       = x * inv + tgt[b0];
                y[b0 + HW_] = yv * inv + tgt[b0 + HW_];
            }
        }
    }
}

// ============================ instnorm + fold (unchanged) ============================
__global__ void instnorm_stats_kernel(const float* __restrict__ y,
                                      float* __restrict__ mu, float* __restrict__ rs)
{
    const int sc = blockIdx.x;
    const float* row = y + (long)sc * HW_;
    float sum = 0.f, ss = 0.f;
    for (int p = threadIdx.x; p < HW_; p += 256) {
        float v = row[p]; sum += v; ss += v * v;
    }
    __shared__ float s1[256], s2[256];
    s1[threadIdx.x] = sum; s2[threadIdx.x] = ss;
    __syncthreads();
    for (int st = 128; st > 0; st >>= 1) {
        if (threadIdx.x < st) {
            s1[threadIdx.x] += s1[threadIdx.x + st];
            s2[threadIdx.x] += s2[threadIdx.x + st];
        }
        __syncthreads();
    }
    if (threadIdx.x == 0) {
        float m = s1[0] / (float)HW_;
        float var = s2[0] / (float)HW_ - m * m;
        mu[sc] = m; rs[sc] = rsqrtf(var + 1e-5f);
    }
}

__global__ void fold_kernel(const float* __restrict__ WK, const float* __restrict__ bK,
                            const float* __restrict__ mu, const float* __restrict__ rs,
                            float* __restrict__ Wf, float* __restrict__ bf)
{
    const int j = blockIdx.x, s = blockIdx.y, tid = threadIdx.x;
    float w = WK[j * C_ + tid] * rs[s * C_ + tid];
    Wf[((long)(s * KD_ + j)) * C_ + tid] = w;
    __shared__ float red[256];
    red[tid] = w * mu[s * C_ + tid];
    __syncthreads();
    for (int st = 128; st > 0; st >>= 1) {
        if (tid < st) red[tid] += red[tid + st];
        __syncthreads();
    }
    if (tid == 0) bf[s * KD_ + j] = bK[j] - red[0];
}

// ============================ cross attention (R12 structure + exp2f) ============================
// Grid (72, S). 256 thr, 8 warps = (qg 0..1) x (kg 0..3). Block = 32q, all 90 K-tiles.
// Lane (qi=l>>3, ki=l&7): queries {16qg + qi + 4i}, keys {32kg + 8m + ki}.
#define CRK 0
#define CRKSTR 16896          // 128*132
#define CRV 33792
#define CRVSTR 2560           // 128*20
#define CRQ 38912             // 32*132
#define CRM 43136             // 1024 u64 (2048 f) + 128 f
#define CR_TOT 45312
#define CR_NT 90

__device__ __forceinline__ void cross_prefetch(float* sm, int buf, const float* wks,
                                               const float* wvs, int k0, int tid)
{
    float* Kb = sm + CRK + buf * CRKSTR;
    float* Vb = sm + CRV + buf * CRVSTR;
#pragma unroll
    for (int r = 0; r < 16; r++) {
        int idx = r * 256 + tid;
        int k = idx >> 5, u = idx & 31;
        cp16(Kb + k * 132 + 4 * u, wks + (long)(k0 + k) * KD_ + 4 * u);
    }
#pragma unroll
    for (int r = 0; r < 2; r++) {
        int idx = r * 256 + tid;
        int k = idx >> 2, j = idx & 3;
        cp16(Vb + k * 20 + 4 * j, wvs + (long)(k0 + k) * CE_ + 4 * j);
    }
}

__global__ void __launch_bounds__(256, 1)
cross_attn_kernel(const float* __restrict__ wq2, const float* __restrict__ wk2,
                  const float* __restrict__ wv2, float* __restrict__ out)
{
    extern __shared__ float sm[];
    const int s = blockIdx.y, q0 = blockIdx.x * 32;
    const int tid = threadIdx.x, w = tid >> 5, l = tid & 31;
    const int qg = w >> 2, kg = w & 3;
    const int qi = l >> 3, ki = l & 7;
    const float* wqs = wq2 + (long)s * HW_ * KD_;
    const float* wks = wk2 + (long)s * LK_ * KD_;
    const float* wvs = wv2 + (long)s * LK_ * CE_;

    // stage Q (prescaled by 30*log2e), pitch 132
    const float qscale = TAU_INV * LOG2E;
#pragma unroll
    for (int r = 0; r < 4; r++) {
        int idx = r * 256 + tid;
        int q = idx >> 5, u = idx & 31;
        float4 v = *(const float4*)(wqs + (long)(q0 + q) * KD_ + 4 * u);
        v.x *= qscale; v.y *= qscale; v.z *= qscale; v.w *= qscale;
        *(float4*)(sm + CRQ + q * 132 + 4 * u) = v;
    }
    cross_prefetch(sm, 0, wks, wvs, 0, tid);
    CP_COMMIT();

    float lsum[4] = {0.f, 0.f, 0.f, 0.f};
    u64 acc[4][8];
#pragma unroll
    for (int i = 0; i < 4; i++)
#pragma unroll
        for (int jj = 0; jj < 8; jj++) acc[i][jj] = 0ull;

    const float* qbase = sm + CRQ + (16 * qg + qi) * 132;
    for (int kt = 0; kt < CR_NT; kt++) {
        const int cur = kt & 1;
        __syncthreads();
        if (kt + 1 < CR_NT)
            cross_prefetch(sm, cur ^ 1, wks, wvs, (kt + 1) * 128, tid);
        CP_COMMIT();
        CP_WAIT1();
        __syncthreads();

        const float* Kb = sm + CRK + cur * CRKSTR + (32 * kg + ki) * 132;
        const float* Vb = sm + CRV + cur * CRVSTR + (32 * kg + ki) * 20;

        // ---- scores: 4q x 4k per lane ----
        u64 sc[4][4];
#pragma unroll
        for (int i = 0; i < 4; i++)
#pragma unroll
            for (int m = 0; m < 4; m++) sc[i][m] = 0ull;

#pragma unroll 4
        for (int u = 0; u < 32; u++) {
            ulonglong2 qch[4], kch[4];
#pragma unroll
            for (int i = 0; i < 4; i++)
                qch[i] = *(const ulonglong2*)(qbase + (4 * i) * 132 + 4 * u);
#pragma unroll
            for (int m = 0; m < 4; m++)
                kch[m] = *(const ulonglong2*)(Kb + (8 * m) * 132 + 4 * u);
#pragma unroll
            for (int i = 0; i < 4; i++)
#pragma unroll
                for (int m = 0; m < 4; m++) {
                    fma2(sc[i][m], qch[i].x, kch[m].x);
                    fma2(sc[i][m], qch[i].y, kch[m].y);
                }
        }

        // ---- exp2 + PV ----
#pragma unroll
        for (int m = 0; m < 4; m++) {
            const float* vr = Vb + (8 * m) * 20;
            ulonglong2 vA = *(const ulonglong2*)(vr);
            ulonglong2 vB = *(const ulonglong2*)(vr + 4);
            ulonglong2 vC = *(const ulonglong2*)(vr + 8);
            ulonglong2 vD = *(const ulonglong2*)(vr + 12);
#pragma unroll
            for (int i = 0; i < 4; i++) {
                float x, yv; unpack2(sc[i][m], x, yv);
                float p = exp2f((x + yv) - CBIAS);
                lsum[i] += p;
                u64 pk = pack2(p);
                fma2(acc[i][0], pk, vA.x); fma2(acc[i][1], pk, vA.y);
                fma2(acc[i][2], pk, vB.x); fma2(acc[i][3], pk, vB.y);
                fma2(acc[i][4], pk, vC.x); fma2(acc[i][5], pk, vC.y);
                fma2(acc[i][6], pk, vD.x); fma2(acc[i][7], pk, vD.y);
            }
        }
    }

    // ---- butterfly over ki (bits 0..2) ----
#pragma unroll
    for (int off = 4; off; off >>= 1) {
#pragma unroll
        for (int i = 0; i < 4; i++) {
            lsum[i] += __shfl_xor_sync(0xffffffffu, lsum[i], off);
#pragma unroll
            for (int jj = 0; jj < 8; jj++)
                acc[i][jj] = add2(acc[i][jj],
                                  __shfl_xor_sync(0xffffffffu, acc[i][jj], off));
        }
    }

    // ---- kg merge via smem ----
    __syncthreads();
    u64*  mrg  = reinterpret_cast<u64*>(sm + CRM);     // [(qg*4+kg)*16 + qloc][8]
    float* mrgL = sm + CRM + 2048;
    if (ki == 0) {
#pragma unroll
        for (int i = 0; i < 4; i++) {
            int qloc = 4 * i + qi;
            int base = ((qg * 4 + kg) * 16 + qloc) * 8;
#pragma unroll
            for (int jj = 0; jj < 8; jj++) mrg[base + jj] = acc[i][jj];
            mrgL[(qg * 4 + kg) * 16 + qloc] = lsum[i];
        }
    }
    __syncthreads();
    {
        int q32 = tid >> 3, dp = tid & 7;
        int qg2 = q32 >> 4, qloc = q32 & 15;
        u64 tot = 0ull;
        float lt = 0.f;
#pragma unroll
        for (int g = 0; g < 4; g++) {
            tot = add2(tot, mrg[((qg2 * 4 + g) * 16 + qloc) * 8 + dp]);
            lt += mrgL[(qg2 * 4 + g) * 16 + qloc];
        }
        float inv = 1.f / lt;
        float x, yv; unpack2(tot, x, yv);
        int p = q0 + q32;
        out[((long)(s * CE_ + 2 * dp    )) * HW_ + p] = x * inv;
        out[((long)(s * CE_ + 2 * dp + 1)) * HW_ + p] = yv * inv;
    }
}

// ============================ launcher ============================
extern "C" void kernel_launch(void* const* d_in, const int* in_sizes, int n_in,
                              void* d_out, int out_size)
{
    const float* tgt    = (const float*)d_in[0];
    const float* memory = (const float*)d_in[1];
    const float* pos    = (const float*)d_in[2];
    const float* WKs_w  = (const float*)d_in[3];
    const float* WKs_b  = (const float*)d_in[4];
    const float* WVs_w  = (const float*)d_in[5];
    const float* WVs_b  = (const float*)d_in[6];
    const float* WKc_w  = (const float*)d_in[7];
    const float* WKc_b  = (const float*)d_in[8];
    const float* WVc_w  = (const float*)d_in[9];
    const float* WVc_b  = (const float*)d_in[10];
    float* out = (float*)d_out;

    float *p_wq, *p_wv, *p_y, *p_wq2, *p_wk2, *p_wv2, *p_mu, *p_rs, *p_wf, *p_bf;
    cudaGetSymbolAddress((void**)&p_wq,  g_wq);
    cudaGetSymbolAddress((void**)&p_wv,  g_wv);
    cudaGetSymbolAddress((void**)&p_y,   g_y);
    cudaGetSymbolAddress((void**)&p_wq2, g_wq2);
    cudaGetSymbolAddress((void**)&p_wk2, g_wk2);
    cudaGetSymbolAddress((void**)&p_wv2, g_wv2);
    cudaGetSymbolAddress((void**)&p_mu,  g_mu);
    cudaGetSymbolAddress((void**)&p_rs,  g_rs);
    cudaGetSymbolAddress((void**)&p_wf,  g_wf);
    cudaGetSymbolAddress((void**)&p_bf,  g_bf);

    const int SELF_SH  = SF_TOT * 4;   // 223616 B
    const int CROSS_SH = CR_TOT * 4;   // 181248 B
    const int PROJ_SH  = P2_TOT * 4;   // 200704 B
    cudaFuncSetAttribute(self_attn_kernel,  cudaFuncAttributeMaxDynamicSharedMemorySize, SELF_SH);
    cudaFuncSetAttribute(cross_attn_kernel, cudaFuncAttributeMaxDynamicSharedMemorySize, CROSS_SH);
    cudaFuncSetAttribute(proj2_kernel<0, true >, cudaFuncAttributeMaxDynamicSharedMemorySize, PROJ_SH);
    cudaFuncSetAttribute(proj2_kernel<0, false>, cudaFuncAttributeMaxDynamicSharedMemorySize, PROJ_SH);
    cudaFuncSetAttribute(proj2_kernel<1, true >, cudaFuncAttributeMaxDynamicSharedMemorySize, PROJ_SH);

    proj2_kernel<0, true ><<<dim3(HW_/64, S_, 1), 256, PROJ_SH>>>(tgt, WKs_w, WKs_b, p_wq, HW_, 0, 0, 128);
    proj2_kernel<0, false><<<dim3(HW_/64, S_, 2), 256, PROJ_SH>>>(tgt, WVs_w, WVs_b, p_wv, HW_, 0, 0, 256);
    proj_kernel<16, 1, false><<<dim3(LK_/16, S_), 256>>>(pos, WVc_w, WVc_b, p_wv2, CE_, LK_, 0, 0);
    proj2_kernel<1, true ><<<dim3(LK_/64, S_, 1), 256, PROJ_SH>>>(memory, WKc_w, WKc_b, p_wk2, LK_, 0, 0, 128);
    self_attn_kernel<<<dim3(HW_/32, S_), 256, SELF_SH>>>(p_wq, p_wv, tgt, p_y);
    instnorm_stats_kernel<<<S_*C_, 256>>>(p_y, p_mu, p_rs);
    fold_kernel<<<dim3(KD_, S_), 256>>>(WKc_w, WKc_b, p_mu, p_rs, p_wf, p_bf);
    proj2_kernel<0, true ><<<dim3(HW_/64, S_, 1), 256, PROJ_SH>>>(p_y, p_wf, p_bf, p_wq2, HW_, KD_*C_, KD_, 128);
    cross_attn_kernel<<<dim3(HW_/32, S_), 256, CROSS_SH>>>(p_wq2, p_wk2, p_wv2, out);
}

// round 17
// speedup vs baseline: 1.1316x; 1.0177x over previous
#include <cuda_runtime.h>
#include <math.h>

#define S_   2
#define C_   256
#define KD_  128
#define CE_  16
#define F_   5
#define HW_  2304
#define LK_  (F_*HW_)
#define TAU_INV 30.0f
#define LOG2E 1.4426950408889634f
#define CBIAS (30.0f * LOG2E)

typedef unsigned long long u64;

__device__ __forceinline__ u64 pack2(float x) {
    u64 r; asm("mov.b64 %0, {%1, %1};" : "=l"(r) : "f"(x)); return r;
}
__device__ __forceinline__ void unpack2(u64 v, float &x, float &y) {
    asm("mov.b64 {%0, %1}, %2;" : "=f"(x), "=f"(y) : "l"(v));
}
__device__ __forceinline__ void fma2(u64 &d, u64 a, u64 b) {
    asm("fma.rn.f32x2 %0, %1, %2, %0;" : "+l"(d) : "l"(a), "l"(b));
}
__device__ __forceinline__ u64 add2(u64 a, u64 b) {
    u64 r; asm("add.rn.f32x2 %0, %1, %2;" : "=l"(r) : "l"(a), "l"(b)); return r;
}
__device__ __forceinline__ void cp16(float* dst, const float* src) {
    unsigned sa = (unsigned)__cvta_generic_to_shared(dst);
    asm volatile("cp.async.cg.shared.global [%0], [%1], 16;" :: "r"(sa), "l"(src));
}
#define CP_COMMIT() asm volatile("cp.async.commit_group;" ::: "memory")
#define CP_WAIT1()  asm volatile("cp.async.wait_group 1;" ::: "memory")
#define CP_WAIT0()  asm volatile("cp.async.wait_group 0;" ::: "memory")

__device__ float g_wq [S_*HW_*KD_];
__device__ float g_wv [S_*HW_*C_];
__device__ float g_y  [S_*C_*HW_];
__device__ float g_wq2[S_*HW_*KD_];
__device__ float g_wk2[S_*LK_*KD_];
__device__ float g_wv2[S_*LK_*CE_];
__device__ float g_mu [S_*C_];
__device__ float g_rs [S_*C_];
__device__ float g_wf [S_*KD_*C_];
__device__ float g_bf [S_*KD_];

// ============================ proj2 (R16, unchanged) ============================
#define P2PITCH 260
#define P2_SHW  0
#define P2_SHIN (128*P2PITCH)
#define P2_NRM  (P2_SHIN + 64*P2PITCH)
#define P2_TOT  (P2_NRM + 256)

template<int MODE, bool NORM>
__global__ void __launch_bounds__(256, 1)
proj2_kernel(const float* __restrict__ in, const float* __restrict__ Wg,
             const float* __restrict__ Bg, float* __restrict__ out,
             int P, int wstride, int bstride, int Jtot)
{
    extern __shared__ float smp[];
    const int s  = blockIdx.y;
    const int jh = blockIdx.z;
    const int p0 = blockIdx.x * 64;
    const int tid = threadIdx.x, w = tid >> 5, l = tid & 31;
    const int pg = w >> 2, jg = w & 3;
    const int pi = l >> 3, ji = l & 7;

    const float* Wp = Wg + (long)s * wstride + (long)jh * 128 * C_;
    const float* Bp = Bg + (long)s * bstride + jh * 128;

    for (int idx = tid; idx < 128 * 64; idx += 256) {
        int j = idx >> 6, c = idx & 63;
        cp16(smp + P2_SHW + j * P2PITCH + 4 * c, Wp + (long)j * C_ + 4 * c);
    }
    CP_COMMIT();

    {
        int pl = tid & 63, g = tid >> 6;
        long base, stride;
        if (MODE == 0) {
            base = ((long)s * C_) * P + p0 + pl;
            stride = P;
        } else {
            int f = p0 / HW_;
            int hw = p0 - f * HW_ + pl;
            base = ((long)((f * 2 + s) * C_)) * HW_ + hw;
            stride = HW_;
        }
#pragma unroll
        for (int cc = 0; cc < 16; cc++) {
            int i0 = 64 * g + 4 * cc;
            float4 v;
            v.x = in[base + (long)(i0 + 0) * stride];
            v.y = in[base + (long)(i0 + 1) * stride];
            v.z = in[base + (long)(i0 + 2) * stride];
            v.w = in[base + (long)(i0 + 3) * stride];
            *(float4*)(smp + P2_SHIN + pl * P2PITCH + i0) = v;
        }
    }
    CP_WAIT0();
    __syncthreads();

    u64 sc[8][4];
#pragma unroll
    for (int i = 0; i < 8; i++)
#pragma unroll
        for (int m = 0; m < 4; m++) sc[i][m] = 0ull;

    const float* pb = smp + P2_SHIN + (32 * pg + pi) * P2PITCH;
    const float* wb = smp + P2_SHW  + (32 * jg + ji) * P2PITCH;
#pragma unroll 2
    for (int u = 0; u < 64; u++) {
        ulonglong2 a[8], b[4];
#pragma unroll
        for (int i = 0; i < 8; i++)
            a[i] = *(const ulonglong2*)(pb + (4 * i) * P2PITCH + 4 * u);
#pragma unroll
        for (int m = 0; m < 4; m++)
            b[m] = *(const ulonglong2*)(wb + (8 * m) * P2PITCH + 4 * u);
#pragma unroll
        for (int i = 0; i < 8; i++)
#pragma unroll
            for (int m = 0; m < 4; m++) {
                fma2(sc[i][m], a[i].x, b[m].x);
                fma2(sc[i][m], a[i].y, b[m].y);
            }
    }

    float bj[4];
#pragma unroll
    for (int m = 0; m < 4; m++) bj[m] = Bp[32 * jg + 8 * m + ji];

    float val[8][4];
#pragma unroll
    for (int i = 0; i < 8; i++)
#pragma unroll
        for (int m = 0; m < 4; m++) {
            float x, yv; unpack2(sc[i][m], x, yv);
            val[i][m] = x + yv + bj[m];
        }

    if (NORM) {
        float ss[8];
#pragma unroll
        for (int i = 0; i < 8; i++) {
            float t = 0.f;
#pragma unroll
            for (int m = 0; m < 4; m++) t += val[i][m] * val[i][m];
            ss[i] = t;
        }
#pragma unroll
        for (int off = 4; off; off >>= 1)
#pragma unroll
            for (int i = 0; i < 8; i++)
                ss[i] += __shfl_xor_sync(0xffffffffu, ss[i], off);
        if (ji == 0) {
#pragma unroll
            for (int i = 0; i < 8; i++)
                smp[P2_NRM + jg * 64 + 32 * pg + pi + 4 * i] = ss[i];
        }
        __syncthreads();
#pragma unroll
        for (int i = 0; i < 8; i++) {
            int pp = 32 * pg + pi + 4 * i;
            float tot = smp[P2_NRM + pp] + smp[P2_NRM + 64 + pp]
                      + smp[P2_NRM + 128 + pp] + smp[P2_NRM + 192 + pp];
            float rn = 1.f / fmaxf(sqrtf(tot), 1e-12f);
            long ob = ((long)s * P + p0 + pp) * Jtot + jh * 128;
#pragma unroll
            for (int m = 0; m < 4; m++)
                out[ob + 32 * jg + 8 * m + ji] = val[i][m] * rn;
        }
    } else {
#pragma unroll
        for (int i = 0; i < 8; i++) {
            int pp = 32 * pg + pi + 4 * i;
            long ob = ((long)s * P + p0 + pp) * Jtot + jh * 128;
#pragma unroll
            for (int m = 0; m < 4; m++)
                out[ob + 32 * jg + 8 * m + ji] = val[i][m];
        }
    }
}

// ============================ pos projection: 16x16, thread-per-position ============================
__global__ void posproj_kernel(const float* __restrict__ pos, const float* __restrict__ Wg,
                               const float* __restrict__ Bg, float* __restrict__ out)
{
    __shared__ float shW[256];
    __shared__ float shB[16];
    const int tid = threadIdx.x;
    if (tid < 256) shW[tid] = Wg[tid];
    if (tid < 16)  shB[tid] = Bg[tid];
    __syncthreads();

    const int s = blockIdx.y;
    const int p = blockIdx.x * 256 + tid;      // 0..LK-1
    const int f = p / HW_, hw = p - f * HW_;
    const float* base = pos + ((long)((f * 2 + s) * CE_)) * HW_ + hw;

    float xin[16];
#pragma unroll
    for (int i = 0; i < 16; i++) xin[i] = base[(long)i * HW_];

    float* ob = out + ((long)s * LK_ + p) * CE_;
#pragma unroll
    for (int j4 = 0; j4 < 4; j4++) {
        float4 o;
        float* oj = (float*)&o;
#pragma unroll
        for (int jj = 0; jj < 4; jj++) {
            int j = j4 * 4 + jj;
            float acc = shB[j];
#pragma unroll
            for (int i = 0; i < 16; i++) acc += shW[j * 16 + i] * xin[i];
            oj[jj] = acc;
        }
        *(float4*)(ob + 4 * j4) = o;
    }
}

// ============================ self attention (exp2f, reg lsum, syncwarp) ============================
#define SFK 0
#define SFKSTR 8448
#define SFV 16896
#define SFVSTR 16384
#define SFQ 49664
#define SFP 53760
#define SFL 55840
#define SF_TOT 55904
#define SF_NT 36

__device__ __forceinline__ void self_prefetch(float* sm, int buf, const float* wqs,
                                              const float* wvs, int k0, int tid)
{
    float* Kb = sm + SFK + buf * SFKSTR;
    float* Vb = sm + SFV + buf * SFVSTR;
#pragma unroll
    for (int r = 0; r < 8; r++) {
        int idx = r * 256 + tid;
        int k = idx >> 5, u = idx & 31;
        cp16(Kb + k * 132 + 4 * u, wqs + (long)(k0 + k) * KD_ + 4 * u);
    }
#pragma unroll
    for (int r = 0; r < 16; r++) {
        int idx = r * 256 + tid;
        int k = idx >> 6, u = idx & 63;
        cp16(Vb + k * 256 + 4 * u, wvs + (long)(k0 + k) * C_ + 4 * u);
    }
}

__global__ void __launch_bounds__(256, 1)
self_attn_kernel(const float* __restrict__ wq, const float* __restrict__ wv,
                 const float* __restrict__ tgt, float* __restrict__ y)
{
    extern __shared__ float sm[];
    const int s = blockIdx.y, q0 = blockIdx.x * 32;
    const int tid = threadIdx.x, w = tid >> 5, l = tid & 31;
    const int qg = w >> 1, kh = w & 1;
    const float* wqs = wq + (long)s * HW_ * KD_;
    const float* wvs = wv + (long)s * HW_ * C_;
    const float qscale = TAU_INV * LOG2E;

#pragma unroll
    for (int r = 0; r < 4; r++) {
        int idx = r * 256 + tid;
        int q = idx >> 5, u = idx & 31;
        float4 v = *(const float4*)(wqs + (long)(q0 + q) * KD_ + 4 * u);
        v.x *= qscale; v.y *= qscale; v.z *= qscale; v.w *= qscale;
        *(float4*)(sm + SFQ + q * 128 + 4 * u) = v;
    }
    self_prefetch(sm, 0, wqs, wvs, 0, tid);
    CP_COMMIT();

    float lsum8[8];
#pragma unroll
    for (int i = 0; i < 8; i++) lsum8[i] = 0.f;
    u64 acc[8][4];
#pragma unroll
    for (int i = 0; i < 8; i++)
#pragma unroll
        for (int jj = 0; jj < 4; jj++) acc[i][jj] = 0ull;

    for (int kt = 0; kt < SF_NT; kt++) {
        const int cur = kt & 1;
        __syncthreads();
        if (kt + 1 < SF_NT)
            self_prefetch(sm, cur ^ 1, wqs, wvs, (kt + 1) * 64, tid);
        CP_COMMIT();
        CP_WAIT1();
        __syncthreads();

        const float* Kb = sm + SFK + cur * SFKSTR;
        const float* Vb = sm + SFV + cur * SFVSTR;

        u64 sc[8];
#pragma unroll
        for (int i = 0; i < 8; i++) sc[i] = 0ull;
        const float* krow = Kb + (32 * kh + l) * 132;
#pragma unroll 4
        for (int u = 0; u < 32; u++) {
            ulonglong2 ka = *(const ulonglong2*)(krow + 4 * u);
#pragma unroll
            for (int i = 0; i < 8; i++) {
                ulonglong2 qv = *(const ulonglong2*)(sm + SFQ + (8 * qg + i) * 128 + 4 * u);
                fma2(sc[i], qv.x, ka.x); fma2(sc[i], qv.y, ka.y);
            }
        }
        // softmax: p = exp2(s - 30*log2e); partial lsum stays in registers
#pragma unroll
        for (int i = 0; i < 8; i++) {
            float x, yv; unpack2(sc[i], x, yv);
            float p = exp2f((x + yv) - CBIAS);
            sm[SFP + (8 * qg + i) * 65 + 32 * kh + l] = p;
            lsum8[i] += p;
        }
        __syncwarp();      // P rows are warp-private; block barrier unnecessary

#pragma unroll 2
        for (int kk = 0; kk < 32; kk++) {
            const int k = 32 * kh + kk;
            u64 pk[8];
#pragma unroll
            for (int i = 0; i < 8; i++)
                pk[i] = pack2(sm[SFP + (8 * qg + i) * 65 + k]);
            const float* vr = Vb + k * 256 + 2 * l;
#pragma unroll
            for (int jj = 0; jj < 4; jj++) {
                u64 vv = *(const u64*)(vr + 64 * jj);
#pragma unroll
                for (int i = 0; i < 8; i++) fma2(acc[i][jj], pk[i], vv);
            }
        }
    }

    // one-time lsum butterfly
#pragma unroll
    for (int off = 16; off; off >>= 1)
#pragma unroll
        for (int i = 0; i < 8; i++)
            lsum8[i] += __shfl_xor_sync(0xffffffffu, lsum8[i], off);

    __syncthreads();
    u64* sbuf = reinterpret_cast<u64*>(sm + SFK);
    float* lbuf = sm + SFL;
    if (kh == 0) {
#pragma unroll
        for (int i = 0; i < 8; i++)
#pragma unroll
            for (int jj = 0; jj < 4; jj++)
                sbuf[((qg * 32 + l) * 33) + i * 4 + jj] = acc[i][jj];
        if (l == 0) {
#pragma unroll
            for (int i = 0; i < 8; i++) lbuf[qg * 8 + i] = lsum8[i];
        }
    }
    __syncthreads();
    if (kh == 1) {
#pragma unroll
        for (int i = 0; i < 8; i++) {
            float inv = 1.f / (lsum8[i] + lbuf[qg * 8 + i]);
            int p = q0 + 8 * qg + i;
#pragma unroll
            for (int jj = 0; jj < 4; jj++) {
                u64 t = add2(acc[i][jj], sbuf[((qg * 32 + l) * 33) + i * 4 + jj]);
                float x, yv; unpack2(t, x, yv);
                int d = 2 * l + 64 * jj;
                long b0 = ((long)(s * C_ + d)) * HW_ + p;
                y[b0]       = x * inv + tgt[b0];
                y[b0 + HW_] = yv * inv + tgt[b0 + HW_];
            }
        }
    }
}

// ============================ instnorm + fold (unchanged) ============================
__global__ void instnorm_stats_kernel(const float* __restrict__ y,
                                      float* __restrict__ mu, float* __restrict__ rs)
{
    const int sc = blockIdx.x;
    const float* row = y + (long)sc * HW_;
    float sum = 0.f, ss = 0.f;
    for (int p = threadIdx.x; p < HW_; p += 256) {
        float v = row[p]; sum += v; ss += v * v;
    }
    __shared__ float s1[256], s2[256];
    s1[threadIdx.x] = sum; s2[threadIdx.x] = ss;
    __syncthreads();
    for (int st = 128; st > 0; st >>= 1) {
        if (threadIdx.x < st) {
            s1[threadIdx.x] += s1[threadIdx.x + st];
            s2[threadIdx.x] += s2[threadIdx.x + st];
        }
        __syncthreads();
    }
    if (threadIdx.x == 0) {
        float m = s1[0] / (float)HW_;
        float var = s2[0] / (float)HW_ - m * m;
        mu[sc] = m; rs[sc] = rsqrtf(var + 1e-5f);
    }
}

__global__ void fold_kernel(const float* __restrict__ WK, const float* __restrict__ bK,
                            const float* __restrict__ mu, const float* __restrict__ rs,
                            float* __restrict__ Wf, float* __restrict__ bf)
{
    const int j = blockIdx.x, s = blockIdx.y, tid = threadIdx.x;
    float w = WK[j * C_ + tid] * rs[s * C_ + tid];
    Wf[((long)(s * KD_ + j)) * C_ + tid] = w;
    __shared__ float red[256];
    red[tid] = w * mu[s * C_ + tid];
    __syncthreads();
    for (int st = 128; st > 0; st >>= 1) {
        if (tid < st) red[tid] += red[tid + st];
        __syncthreads();
    }
    if (tid == 0) bf[s * KD_ + j] = bK[j] - red[0];
}

// ============================ cross attention (R16, unchanged) ============================
#define CRK 0
#define CRKSTR 16896
#define CRV 33792
#define CRVSTR 2560
#define CRQ 38912
#define CRM 43136
#define CR_TOT 45312
#define CR_NT 90

__device__ __forceinline__ void cross_prefetch(float* sm, int buf, const float* wks,
                                               const float* wvs, int k0, int tid)
{
    float* Kb = sm + CRK + buf * CRKSTR;
    float* Vb = sm + CRV + buf * CRVSTR;
#pragma unroll
    for (int r = 0; r < 16; r++) {
        int idx = r * 256 + tid;
        int k = idx >> 5, u = idx & 31;
        cp16(Kb + k * 132 + 4 * u, wks + (long)(k0 + k) * KD_ + 4 * u);
    }
#pragma unroll
    for (int r = 0; r < 2; r++) {
        int idx = r * 256 + tid;
        int k = idx >> 2, j = idx & 3;
        cp16(Vb + k * 20 + 4 * j, wvs + (long)(k0 + k) * CE_ + 4 * j);
    }
}

__global__ void __launch_bounds__(256, 1)
cross_attn_kernel(const float* __restrict__ wq2, const float* __restrict__ wk2,
                  const float* __restrict__ wv2, float* __restrict__ out)
{
    extern __shared__ float sm[];
    const int s = blockIdx.y, q0 = blockIdx.x * 32;
    const int tid = threadIdx.x, w = tid >> 5, l = tid & 31;
    const int qg = w >> 2, kg = w & 3;
    const int qi = l >> 3, ki = l & 7;
    const float* wqs = wq2 + (long)s * HW_ * KD_;
    const float* wks = wk2 + (long)s * LK_ * KD_;
    const float* wvs = wv2 + (long)s * LK_ * CE_;

    const float qscale = TAU_INV * LOG2E;
#pragma unroll
    for (int r = 0; r < 4; r++) {
        int idx = r * 256 + tid;
        int q = idx >> 5, u = idx & 31;
        float4 v = *(const float4*)(wqs + (long)(q0 + q) * KD_ + 4 * u);
        v.x *= qscale; v.y *= qscale; v.z *= qscale; v.w *= qscale;
        *(float4*)(sm + CRQ + q * 132 + 4 * u) = v;
    }
    cross_prefetch(sm, 0, wks, wvs, 0, tid);
    CP_COMMIT();

    float lsum[4] = {0.f, 0.f, 0.f, 0.f};
    u64 acc[4][8];
#pragma unroll
    for (int i = 0; i < 4; i++)
#pragma unroll
        for (int jj = 0; jj < 8; jj++) acc[i][jj] = 0ull;

    const float* qbase = sm + CRQ + (16 * qg + qi) * 132;
    for (int kt = 0; kt < CR_NT; kt++) {
        const int cur = kt & 1;
        __syncthreads();
        if (kt + 1 < CR_NT)
            cross_prefetch(sm, cur ^ 1, wks, wvs, (kt + 1) * 128, tid);
        CP_COMMIT();
        CP_WAIT1();
        __syncthreads();

        const float* Kb = sm + CRK + cur * CRKSTR + (32 * kg + ki) * 132;
        const float* Vb = sm + CRV + cur * CRVSTR + (32 * kg + ki) * 20;

        u64 sc[4][4];
#pragma unroll
        for (int i = 0; i < 4; i++)
#pragma unroll
            for (int m = 0; m < 4; m++) sc[i][m] = 0ull;

#pragma unroll 4
        for (int u = 0; u < 32; u++) {
            ulonglong2 qch[4], kch[4];
#pragma unroll
            for (int i = 0; i < 4; i++)
                qch[i] = *(const ulonglong2*)(qbase + (4 * i) * 132 + 4 * u);
#pragma unroll
            for (int m = 0; m < 4; m++)
                kch[m] = *(const ulonglong2*)(Kb + (8 * m) * 132 + 4 * u);
#pragma unroll
            for (int i = 0; i < 4; i++)
#pragma unroll
                for (int m = 0; m < 4; m++) {
                    fma2(sc[i][m], qch[i].x, kch[m].x);
                    fma2(sc[i][m], qch[i].y, kch[m].y);
                }
        }

#pragma unroll
        for (int m = 0; m < 4; m++) {
            const float* vr = Vb + (8 * m) * 20;
            ulonglong2 vA = *(const ulonglong2*)(vr);
            ulonglong2 vB = *(const ulonglong2*)(vr + 4);
            ulonglong2 vC = *(const ulonglong2*)(vr + 8);
            ulonglong2 vD = *(const ulonglong2*)(vr + 12);
#pragma unroll
            for (int i = 0; i < 4; i++) {
                float x, yv; unpack2(sc[i][m], x, yv);
                float p = exp2f((x + yv) - CBIAS);
                lsum[i] += p;
                u64 pk = pack2(p);
                fma2(acc[i][0], pk, vA.x); fma2(acc[i][1], pk, vA.y);
                fma2(acc[i][2], pk, vB.x); fma2(acc[i][3], pk, vB.y);
                fma2(acc[i][4], pk, vC.x); fma2(acc[i][5], pk, vC.y);
                fma2(acc[i][6], pk, vD.x); fma2(acc[i][7], pk, vD.y);
            }
        }
    }

#pragma unroll
    for (int off = 4; off; off >>= 1) {
#pragma unroll
        for (int i = 0; i < 4; i++) {
            lsum[i] += __shfl_xor_sync(0xffffffffu, lsum[i], off);
#pragma unroll
            for (int jj = 0; jj < 8; jj++)
                acc[i][jj] = add2(acc[i][jj],
                                  __shfl_xor_sync(0xffffffffu, acc[i][jj], off));
        }
    }
    __syncthreads();
    u64*  mrg  = reinterpret_cast<u64*>(sm + CRM);
    float* mrgL = sm + CRM + 2048;
    if (ki == 0) {
#pragma unroll
        for (int i = 0; i < 4; i++) {
            int qloc = 4 * i + qi;
            int base = ((qg * 4 + kg) * 16 + qloc) * 8;
#pragma unroll
            for (int jj = 0; jj < 8; jj++) mrg[base + jj] = acc[i][jj];
            mrgL[(qg * 4 + kg) * 16 + qloc] = lsum[i];
        }
    }
    __syncthreads();
    {
        int q32 = tid >> 3, dp = tid & 7;
        int qg2 = q32 >> 4, qloc = q32 & 15;
        u64 tot = 0ull;
        float lt = 0.f;
#pragma unroll
        for (int g = 0; g < 4; g++) {
            tot = add2(tot, mrg[((qg2 * 4 + g) * 16 + qloc) * 8 + dp]);
            lt += mrgL[(qg2 * 4 + g) * 16 + qloc];
        }
        float inv = 1.f / lt;
        float x, yv; unpack2(tot, x, yv);
        int p = q0 + q32;
        out[((long)(s * CE_ + 2 * dp    )) * HW_ + p] = x * inv;
        out[((long)(s * CE_ + 2 * dp + 1)) * HW_ + p] = yv * inv;
    }
}

// ============================ launcher ============================
extern "C" void kernel_launch(void* const* d_in, const int* in_sizes, int n_in,
                              void* d_out, int out_size)
{
    const float* tgt    = (const float*)d_in[0];
    const float* memory = (const float*)d_in[1];
    const float* pos    = (const float*)d_in[2];
    const float* WKs_w  = (const float*)d_in[3];
    const float* WKs_b  = (const float*)d_in[4];
    const float* WVs_w  = (const float*)d_in[5];
    const float* WVs_b  = (const float*)d_in[6];
    const float* WKc_w  = (const float*)d_in[7];
    const float* WKc_b  = (const float*)d_in[8];
    const float* WVc_w  = (const float*)d_in[9];
    const float* WVc_b  = (const float*)d_in[10];
    float* out = (float*)d_out;

    float *p_wq, *p_wv, *p_y, *p_wq2, *p_wk2, *p_wv2, *p_mu, *p_rs, *p_wf, *p_bf;
    cudaGetSymbolAddress((void**)&p_wq,  g_wq);
    cudaGetSymbolAddress((void**)&p_wv,  g_wv);
    cudaGetSymbolAddress((void**)&p_y,   g_y);
    cudaGetSymbolAddress((void**)&p_wq2, g_wq2);
    cudaGetSymbolAddress((void**)&p_wk2, g_wk2);
    cudaGetSymbolAddress((void**)&p_wv2, g_wv2);
    cudaGetSymbolAddress((void**)&p_mu,  g_mu);
    cudaGetSymbolAddress((void**)&p_rs,  g_rs);
    cudaGetSymbolAddress((void**)&p_wf,  g_wf);
    cudaGetSymbolAddress((void**)&p_bf,  g_bf);

    const int SELF_SH  = SF_TOT * 4;
    const int CROSS_SH = CR_TOT * 4;
    const int PROJ_SH  = P2_TOT * 4;
    cudaFuncSetAttribute(self_attn_kernel,  cudaFuncAttributeMaxDynamicSharedMemorySize, SELF_SH);
    cudaFuncSetAttribute(cross_attn_kernel, cudaFuncAttributeMaxDynamicSharedMemorySize, CROSS_SH);
    cudaFuncSetAttribute(proj2_kernel<0, true >, cudaFuncAttributeMaxDynamicSharedMemorySize, PROJ_SH);
    cudaFuncSetAttribute(proj2_kernel<0, false>, cudaFuncAttributeMaxDynamicSharedMemorySize, PROJ_SH);
    cudaFuncSetAttribute(proj2_kernel<1, true >, cudaFuncAttributeMaxDynamicSharedMemorySize, PROJ_SH);

    proj2_kernel<0, true ><<<dim3(HW_/64, S_, 1), 256, PROJ_SH>>>(tgt, WKs_w, WKs_b, p_wq, HW_, 0, 0, 128);
    proj2_kernel<0, false><<<dim3(HW_/64, S_, 2), 256, PROJ_SH>>>(tgt, WVs_w, WVs_b, p_wv, HW_, 0, 0, 256);
    posproj_kernel<<<dim3(LK_/256, S_), 256>>>(pos, WVc_w, WVc_b, p_wv2);
    proj2_kernel<1, true ><<<dim3(LK_/64, S_, 1), 256, PROJ_SH>>>(memory, WKc_w, WKc_b, p_wk2, LK_, 0, 0, 128);
    self_attn_kernel<<<dim3(HW_/32, S_), 256, SELF_SH>>>(p_wq, p_wv, tgt, p_y);
    instnorm_stats_kernel<<<S_*C_, 256>>>(p_y, p_mu, p_rs);
    fold_kernel<<<dim3(KD_, S_), 256>>>(WKc_w, WKc_b, p_mu, p_rs, p_wf, p_bf);
    proj2_kernel<0, true ><<<dim3(HW_/64, S_, 1), 256, PROJ_SH>>>(p_y, p_wf, p_bf, p_wq2, HW_, KD_*C_, KD_, 128);
    cross_attn_kernel<<<dim3(HW_/32, S_), 256, CROSS_SH>>>(p_wq2, p_wk2, p_wv2, out);
}